// round 15
// baseline (speedup 1.0000x reference)
#include <cuda_runtime.h>
#include <cuda_fp16.h>
#include <mma.h>
#include <math.h>
#include <stdint.h>

using namespace nvcuda;

#define BATCH 2
#define NPTS  16384
#define KNB   32
#define C     128
#define MTOT  (BATCH*NPTS)   // 32768
#define LN_EPS 1e-5f

// scratch (device globals; no runtime allocation)
__device__ __half g_h [(size_t)MTOT*C];   // 8 MB, s in fp16
__device__ __half g_r [(size_t)MTOT*C];   // 8 MB, res in fp16
__device__ __half g_wo[(size_t)C*C];      // w_out in fp16
__device__ float  g_A [3*C];
__device__ float  g_wd[C];
__device__ float  g_b2[C];

#define ALD 136                     // a/b smem pitch in halves (272 B)
#define CLD 132                     // c  smem pitch in floats (528 B)
#define GS_SMEM  52224                                      // 64xALD + 128xALD halves
#define LN_SMEM  ((128*CLD + 128 + 128 + 256 + 256) * 4)    // 70656 B

// ---------------------------------------------------------------------------
// K1 (wmma, occ-4 single wave): s = (feat + pts·wp_nbr) @ w_gcm -> fp16 g_h.
// CTA tile 64x128, 8 warps each 32x32. CTA 0 also computes pool constants.
// ---------------------------------------------------------------------------
__global__ __launch_bounds__(256, 4) void k_gemm_s(
    const float* __restrict__ feat, const float* __restrict__ wg,
    const float* __restrict__ pts,
    const float* __restrict__ w_pos, const float* __restrict__ b_pos,
    const float* __restrict__ b_gcm)
{
    extern __shared__ char dyn[];
    __half* a_sm = (__half*)dyn;                    // [64][ALD]
    __half* b_sm = (__half*)dyn + 64*ALD;           // [128][ALD]

    __shared__ float wp_c[3][C];

    const int tid  = threadIdx.x;
    const int wid  = tid >> 5;
    const int row0 = blockIdx.x * 64;

    if (tid < C) {
#pragma unroll
        for (int d = 0; d < 3; d++)
            wp_c[d][tid] = w_pos[(3+d)*C + tid] + w_pos[(6+d)*C + tid];
    }
    __syncthreads();

    // stage A = fp16(feat + pts·wp_c)  (64x128 -> 2048 float4)
#pragma unroll
    for (int it = 0; it < 8; it++) {
        int idx = tid + it * 256;
        int r = idx >> 5, c4 = (idx & 31) << 2;
        int gr = row0 + r;
        float4 v = *(const float4*)&feat[(size_t)gr*C + c4];
        float px = pts[gr*3 + 0], py = pts[gr*3 + 1], pz = pts[gr*3 + 2];
        float4 w0 = *(const float4*)&wp_c[0][c4];
        float4 w1 = *(const float4*)&wp_c[1][c4];
        float4 w2 = *(const float4*)&wp_c[2][c4];
        v.x = fmaf(px, w0.x, fmaf(py, w1.x, fmaf(pz, w2.x, v.x)));
        v.y = fmaf(px, w0.y, fmaf(py, w1.y, fmaf(pz, w2.y, v.y)));
        v.z = fmaf(px, w0.z, fmaf(py, w1.z, fmaf(pz, w2.z, v.z)));
        v.w = fmaf(px, w0.w, fmaf(py, w1.w, fmaf(pz, w2.w, v.w)));
        __half2 h0 = __floats2half2_rn(v.x, v.y);
        __half2 h1 = __floats2half2_rn(v.z, v.w);
        uint2 o; o.x = *(unsigned*)&h0; o.y = *(unsigned*)&h1;
        *(uint2*)&a_sm[r*ALD + c4] = o;
    }
    // stage B = fp16(w_gcm)
#pragma unroll
    for (int it = 0; it < 16; it++) {
        int idx = tid + it * 256;
        int k = idx >> 5, c4 = (idx & 31) << 2;
        float4 w = *(const float4*)&wg[(size_t)k*C + c4];
        __half2 q0 = __floats2half2_rn(w.x, w.y);
        __half2 q1 = __floats2half2_rn(w.z, w.w);
        uint2 ow; ow.x = *(unsigned*)&q0; ow.y = *(unsigned*)&q1;
        *(uint2*)&b_sm[k*ALD + c4] = ow;
    }
    __syncthreads();

    const int wm = wid >> 2;     // 0..1 -> rows 32*wm
    const int wn = wid & 3;      // 0..3 -> cols 32*wn

    wmma::fragment<wmma::accumulator, 16, 16, 16, float> acc[2][2];
#pragma unroll
    for (int i = 0; i < 2; i++)
#pragma unroll
        for (int j = 0; j < 2; j++) wmma::fill_fragment(acc[i][j], 0.f);

#pragma unroll
    for (int kk = 0; kk < 8; kk++) {
        wmma::fragment<wmma::matrix_a, 16, 16, 16, __half, wmma::row_major> af[2];
        wmma::fragment<wmma::matrix_b, 16, 16, 16, __half, wmma::row_major> bf[2];
#pragma unroll
        for (int i = 0; i < 2; i++)
            wmma::load_matrix_sync(af[i], &a_sm[(wm*32 + i*16)*ALD + kk*16], ALD);
#pragma unroll
        for (int j = 0; j < 2; j++)
            wmma::load_matrix_sync(bf[j], &b_sm[(kk*16)*ALD + wn*32 + j*16], ALD);
#pragma unroll
        for (int i = 0; i < 2; i++)
#pragma unroll
            for (int j = 0; j < 2; j++)
                wmma::mma_sync(acc[i][j], af[i], bf[j], acc[i][j]);
    }
    __syncthreads();

    float* c_sm = (float*)dyn;                      // [64][CLD]
#pragma unroll
    for (int i = 0; i < 2; i++)
#pragma unroll
        for (int j = 0; j < 2; j++)
            wmma::store_matrix_sync(&c_sm[(wm*32 + i*16)*CLD + wn*32 + j*16],
                                    acc[i][j], CLD, wmma::mem_row_major);
    __syncthreads();

#pragma unroll
    for (int it = 0; it < 8; it++) {
        int idx = tid + it * 256;
        int r = idx >> 5, c4 = (idx & 31) << 2;
        float4 v = *(const float4*)&c_sm[r*CLD + c4];
        __half2 h0 = __floats2half2_rn(v.x, v.y);
        __half2 h1 = __floats2half2_rn(v.z, v.w);
        uint2 o; o.x = *(unsigned*)&h0; o.y = *(unsigned*)&h1;
        *(uint2*)&g_h[(size_t)(row0 + r)*C + c4] = o;
    }

    // ---- CTA 0: pool constants (fp32) ----
    if (blockIdx.x == 0) {
        float* part = (float*)dyn;  // 8*256 floats (post-sync reuse)
        __syncthreads();
        const int cc   = tid & 127;
        const int half = tid >> 7;
        const int j0   = half * 64;
        float q[8];
#pragma unroll
        for (int i = 0; i < 8; i++) q[i] = 0.f;
#pragma unroll 4
        for (int jj = 0; jj < 64; jj++) {
            int j = j0 + jj;
            float w = wg[(size_t)j*C + cc];
            q[0] = fmaf(w_pos[0*C + j], w, q[0]);
            q[1] = fmaf(w_pos[1*C + j], w, q[1]);
            q[2] = fmaf(w_pos[2*C + j], w, q[2]);
            q[3] = fmaf(w_pos[6*C + j], w, q[3]);
            q[4] = fmaf(w_pos[7*C + j], w, q[4]);
            q[5] = fmaf(w_pos[8*C + j], w, q[5]);
            q[6] = fmaf(w_pos[9*C + j], w, q[6]);
            q[7] = fmaf(b_pos[j],       w, q[7]);
        }
#pragma unroll
        for (int i = 0; i < 8; i++) part[i*256 + tid] = q[i];
        __syncthreads();
        if (tid < 128) {
            float r[8];
#pragma unroll
            for (int i = 0; i < 8; i++)
                r[i] = part[i*256 + tid] + part[i*256 + tid + 128];
            g_A[0*C + tid] = r[0] - r[3];
            g_A[1*C + tid] = r[1] - r[4];
            g_A[2*C + tid] = r[2] - r[5];
            g_wd[tid]      = r[6];
            g_b2[tid]      = r[7] + b_gcm[tid];
        }
    }
}

// ---------------------------------------------------------------------------
// K2 (pool, standalone, high occupancy): one warp per point, lane = 4 ch.
// First 16 CTAs also pre-convert w_out -> fp16 g_wo (for K3's B staging).
// ---------------------------------------------------------------------------
__global__ __launch_bounds__(256) void k_pool(
    const float* __restrict__ pts, const float* __restrict__ feat,
    const int*   __restrict__ gidx, const float* __restrict__ wout)
{
    if (blockIdx.x < 16) {
        int b = blockIdx.x * 1024 + threadIdx.x * 4;
        float4 v = *(const float4*)&wout[b];
        __half2 h0 = __floats2half2_rn(v.x, v.y);
        __half2 h1 = __floats2half2_rn(v.z, v.w);
        uint2 o; o.x = *(unsigned*)&h0; o.y = *(unsigned*)&h1;
        *(uint2*)&g_wo[b] = o;
    }

    const int pt   = (blockIdx.x * 256 + threadIdx.x) >> 5;  // 0..32767
    const int lane = threadIdx.x & 31;
    const int base = (pt >> 14) << 14;
    const int c0   = lane << 2;

    const float4 wf = *(const float4*)&g_wd[c0];
    const __half2 wd01 = __floats2half2_rn(wf.x, wf.y);
    const __half2 wd23 = __floats2half2_rn(wf.z, wf.w);
    const __half2 ninf = __half2half2(__ushort_as_half(0xFC00));
    const __half* hs = &g_h[0];

    const float cx = pts[pt*3 + 0], cy = pts[pt*3 + 1], cz = pts[pt*3 + 2];
    int j = gidx[pt*KNB + lane] + base;
    const float* gp = &pts[(size_t)j*3];
    float dx = gp[0] - cx, dy = gp[1] - cy, dz = gp[2] - cz;
    float dist = sqrtf(fmaf(dx, dx, fmaf(dy, dy, dz*dz)));
    unsigned p = (unsigned)j
               | ((unsigned)__half_as_ushort(__float2half_rn(dist)) << 16);

    __half2 acc01 = ninf, acc23 = ninf;
#pragma unroll
    for (int k = 0; k < 32; k++) {
        unsigned q = __shfl_sync(0xffffffffu, p, k);
        __half2 d = __half2half2(__ushort_as_half((unsigned short)(q >> 16)));
        uint2 rv = *(const uint2*)(hs + (((q & 0xFFFFu) << 7) + c0));
        acc01 = __hmax2(acc01, __hfma2(d, wd01, *(__half2*)&rv.x));
        acc23 = __hmax2(acc23, __hfma2(d, wd23, *(__half2*)&rv.y));
    }

    float2 m01 = __half22float2(acc01);
    float2 m23 = __half22float2(acc23);

    const float4 a0 = *(const float4*)&g_A[c0];
    const float4 a1 = *(const float4*)&g_A[C + c0];
    const float4 a2 = *(const float4*)&g_A[2*C + c0];
    const float4 b2 = *(const float4*)&g_b2[c0];
    const float4 f  = *(const float4*)&feat[(size_t)pt*C + c0];

    float r0 = fmaxf(m01.x + fmaf(cx, a0.x, fmaf(cy, a1.x, fmaf(cz, a2.x, b2.x))), 0.f) + f.x;
    float r1 = fmaxf(m01.y + fmaf(cx, a0.y, fmaf(cy, a1.y, fmaf(cz, a2.y, b2.y))), 0.f) + f.y;
    float r2 = fmaxf(m23.x + fmaf(cx, a0.z, fmaf(cy, a1.z, fmaf(cz, a2.z, b2.z))), 0.f) + f.z;
    float r3 = fmaxf(m23.y + fmaf(cx, a0.w, fmaf(cy, a1.w, fmaf(cz, a2.w, b2.w))), 0.f) + f.w;

    __half2 h0 = __floats2half2_rn(r0, r1);
    __half2 h1 = __floats2half2_rn(r2, r3);
    uint2 o; o.x = *(unsigned*)&h0; o.y = *(unsigned*)&h1;
    *(uint2*)&g_r[(size_t)pt*C + c0] = o;
}

// ---------------------------------------------------------------------------
// K3 (wmma + LN, 128-row occ-2): out = relu(LN(res @ w_out + b_out)·g + b).
// A and B both staged by straight fp16 uint4 copies.
// ---------------------------------------------------------------------------
__global__ __launch_bounds__(256, 2) void k_gemm_ln(
    const float* __restrict__ bout,
    const float* __restrict__ lng,  const float* __restrict__ lnb,
    float* __restrict__ out)
{
    extern __shared__ char dyn[];
    __half* a_h = (__half*)dyn;                     // [128][ALD]
    __half* b_h = (__half*)dyn + 128*ALD;           // [128][ALD]

    const int tid  = threadIdx.x;
    const int wid  = tid >> 5;
    const int row0 = blockIdx.x * 128;

    // stage A: fp16 res rows
#pragma unroll
    for (int it = 0; it < 8; it++) {
        int idx = tid + it * 256;            // 2048 uint4s
        int r = idx >> 4, c8 = (idx & 15) << 3;
        uint4 v = *(const uint4*)&g_r[(size_t)(row0 + r)*C + c8];
        *(uint4*)&a_h[r*ALD + c8] = v;
    }
    // stage B: fp16 w_out rows
#pragma unroll
    for (int it = 0; it < 8; it++) {
        int idx = tid + it * 256;            // 2048 uint4s
        int k = idx >> 4, c8 = (idx & 15) << 3;
        uint4 v = *(const uint4*)&g_wo[(size_t)k*C + c8];
        *(uint4*)&b_h[k*ALD + c8] = v;
    }
    __syncthreads();

    const int wm = wid >> 1;
    const int wn = wid & 1;

    wmma::fragment<wmma::accumulator, 16, 16, 16, float> acc[2][4];
#pragma unroll
    for (int i = 0; i < 2; i++)
#pragma unroll
        for (int j = 0; j < 4; j++) wmma::fill_fragment(acc[i][j], 0.f);

#pragma unroll
    for (int kk = 0; kk < 8; kk++) {
        wmma::fragment<wmma::matrix_a, 16, 16, 16, __half, wmma::row_major> af[2];
        wmma::fragment<wmma::matrix_b, 16, 16, 16, __half, wmma::row_major> bf[4];
#pragma unroll
        for (int i = 0; i < 2; i++)
            wmma::load_matrix_sync(af[i], &a_h[(wm*32 + i*16)*ALD + kk*16], ALD);
#pragma unroll
        for (int j = 0; j < 4; j++)
            wmma::load_matrix_sync(bf[j], &b_h[(kk*16)*ALD + wn*64 + j*16], ALD);
#pragma unroll
        for (int i = 0; i < 2; i++)
#pragma unroll
            for (int j = 0; j < 4; j++)
                wmma::mma_sync(acc[i][j], af[i], bf[j], acc[i][j]);
    }
    __syncthreads();

    // epilogue: frags -> fp32 smem, bias + LN (256-thread stats) + relu
    float* c_sm = (float*)dyn;                      // [128][CLD]
    float* smu  = (float*)dyn + 128*CLD;            // [128]
    float* srs  = smu + 128;                        // [128]
    float* sp   = srs + 128;                        // [256]
    float* sq   = sp + 256;                         // [256]

#pragma unroll
    for (int i = 0; i < 2; i++)
#pragma unroll
        for (int j = 0; j < 4; j++)
            wmma::store_matrix_sync(&c_sm[(wm*32 + i*16)*CLD + wn*64 + j*16],
                                    acc[i][j], CLD, wmma::mem_row_major);
    __syncthreads();

    {
        int r = tid & 127, half = tid >> 7;
        int cbeg = half * 64;
        float sum = 0.f, ss = 0.f;
#pragma unroll 8
        for (int c = cbeg; c < cbeg + 64; c += 4) {
            float4 x = *(const float4*)&c_sm[r*CLD + c];
            float4 b = *(const float4*)&bout[c];
            float v0 = x.x + b.x, v1 = x.y + b.y, v2 = x.z + b.z, v3 = x.w + b.w;
            sum += v0 + v1 + v2 + v3;
            ss = fmaf(v0, v0, fmaf(v1, v1, fmaf(v2, v2, fmaf(v3, v3, ss))));
        }
        sp[tid] = sum; sq[tid] = ss;
    }
    __syncthreads();
    if (tid < 128) {
        float sum = sp[tid] + sp[tid + 128];
        float ss  = sq[tid] + sq[tid + 128];
        float mu  = sum * (1.f/128.f);
        float var = fmaf(ss, 1.f/128.f, -mu*mu);
        smu[tid] = mu;
        srs[tid] = rsqrtf(var + LN_EPS);
    }
    __syncthreads();

#pragma unroll
    for (int it = 0; it < 16; it++) {
        int idx = tid + it * 256;
        int r = idx >> 5, c4 = (idx & 31) << 2;
        float4 x = *(const float4*)&c_sm[r*CLD + c4];
        float4 bb = *(const float4*)&bout[c4];
        float4 g = *(const float4*)&lng[c4];
        float4 lb = *(const float4*)&lnb[c4];
        float mu = smu[r], rs = srs[r];
        float4 y;
        y.x = fmaxf(fmaf((x.x + bb.x - mu) * rs, g.x, lb.x), 0.f);
        y.y = fmaxf(fmaf((x.y + bb.y - mu) * rs, g.y, lb.y), 0.f);
        y.z = fmaxf(fmaf((x.z + bb.z - mu) * rs, g.z, lb.z), 0.f);
        y.w = fmaxf(fmaf((x.w + bb.w - mu) * rs, g.w, lb.w), 0.f);
        *(float4*)&out[(size_t)(row0 + r)*C + c4] = y;
    }
}

// ---------------------------------------------------------------------------
extern "C" void kernel_launch(void* const* d_in, const int* in_sizes, int n_in,
                              void* d_out, int out_size)
{
    const float* points = (const float*)d_in[0];
    const float* feat   = (const float*)d_in[1];
    const int*   gidx   = (const int*)  d_in[2];
    const float* w_pos  = (const float*)d_in[3];
    const float* b_pos  = (const float*)d_in[4];
    const float* w_gcm  = (const float*)d_in[5];
    const float* b_gcm  = (const float*)d_in[6];
    const float* w_out  = (const float*)d_in[7];
    const float* b_out  = (const float*)d_in[8];
    const float* ln_g   = (const float*)d_in[9];
    const float* ln_b   = (const float*)d_in[10];
    float* out = (float*)d_out;

    cudaFuncSetAttribute(k_gemm_s,  cudaFuncAttributeMaxDynamicSharedMemorySize, GS_SMEM);
    cudaFuncSetAttribute(k_gemm_ln, cudaFuncAttributeMaxDynamicSharedMemorySize, LN_SMEM);

    k_gemm_s <<<MTOT/64,     256, GS_SMEM>>>(feat, w_gcm, points, w_pos, b_pos, b_gcm);
    k_pool   <<<MTOT*32/256, 256>>>(points, feat, gidx, w_out);
    k_gemm_ln<<<MTOT/128,    256, LN_SMEM>>>(b_out, ln_g, ln_b, out);
}

// round 16
// speedup vs baseline: 1.3970x; 1.3970x over previous
#include <cuda_runtime.h>
#include <cuda_fp16.h>
#include <mma.h>
#include <math.h>
#include <stdint.h>

using namespace nvcuda;

#define BATCH 2
#define NPTS  16384
#define KNB   32
#define C     128
#define MTOT  (BATCH*NPTS)   // 32768
#define LN_EPS 1e-5f

// scratch (device globals; no runtime allocation)
__device__ __half g_h [(size_t)MTOT*C];   // 8 MB, s in fp16
__device__ __half g_r [(size_t)MTOT*C];   // 8 MB, res in fp16
__device__ __half g_wo[(size_t)C*C];      // w_out in fp16
__device__ float  g_A [3*C];
__device__ float  g_wd[C];
__device__ float  g_b2[C];

#define ALD 136                     // a/b smem pitch in halves (272 B)
#define CLD 132                     // c  smem pitch in floats (528 B)
#define GS_SMEM  52224                                      // 64xALD + 128xALD halves
#define LN_SMEM  ((128*CLD + 128 + 128 + 256 + 256) * 4)    // 70656 B

// ---------------------------------------------------------------------------
// K1 (wmma, occ-3, batched staging loads): s = (feat + pts·wp_nbr) @ w_gcm.
// CTA tile 64x128, 8 warps each 32x32. CTA 0 also computes pool constants.
// ---------------------------------------------------------------------------
__global__ __launch_bounds__(256, 3) void k_gemm_s(
    const float* __restrict__ feat, const float* __restrict__ wg,
    const float* __restrict__ pts,
    const float* __restrict__ w_pos, const float* __restrict__ b_pos,
    const float* __restrict__ b_gcm)
{
    extern __shared__ char dyn[];
    __half* a_sm = (__half*)dyn;                    // [64][ALD]
    __half* b_sm = (__half*)dyn + 64*ALD;           // [128][ALD]

    __shared__ float wp_c[3][C];

    const int tid  = threadIdx.x;
    const int wid  = tid >> 5;
    const int row0 = blockIdx.x * 64;

    if (tid < C) {
#pragma unroll
        for (int d = 0; d < 3; d++)
            wp_c[d][tid] = w_pos[(3+d)*C + tid] + w_pos[(6+d)*C + tid];
    }
    __syncthreads();

    const int r0 = tid >> 5;             // base row (stride 8 per iter)
    const int c4 = (tid & 31) << 2;      // fixed column

    // ---- stage A: batch all 8 feat loads first (MLP=8), then cvt/store ----
    {
        float4 va[8];
#pragma unroll
        for (int it = 0; it < 8; it++)
            va[it] = *(const float4*)&feat[(size_t)(row0 + r0 + it*8)*C + c4];

        float4 w0 = *(const float4*)&wp_c[0][c4];
        float4 w1 = *(const float4*)&wp_c[1][c4];
        float4 w2 = *(const float4*)&wp_c[2][c4];
#pragma unroll
        for (int it = 0; it < 8; it++) {
            int r = r0 + it*8;
            int gr = row0 + r;
            float px = pts[gr*3 + 0], py = pts[gr*3 + 1], pz = pts[gr*3 + 2];
            float4 v = va[it];
            v.x = fmaf(px, w0.x, fmaf(py, w1.x, fmaf(pz, w2.x, v.x)));
            v.y = fmaf(px, w0.y, fmaf(py, w1.y, fmaf(pz, w2.y, v.y)));
            v.z = fmaf(px, w0.z, fmaf(py, w1.z, fmaf(pz, w2.z, v.z)));
            v.w = fmaf(px, w0.w, fmaf(py, w1.w, fmaf(pz, w2.w, v.w)));
            __half2 h0 = __floats2half2_rn(v.x, v.y);
            __half2 h1 = __floats2half2_rn(v.z, v.w);
            uint2 o; o.x = *(unsigned*)&h0; o.y = *(unsigned*)&h1;
            *(uint2*)&a_sm[r*ALD + c4] = o;
        }
    }
    // ---- stage B: w_gcm in two batches of 8 ----
#pragma unroll
    for (int half = 0; half < 2; half++) {
        float4 vb[8];
#pragma unroll
        for (int it = 0; it < 8; it++) {
            int k = r0 + half*64 + it*8;
            vb[it] = *(const float4*)&wg[(size_t)k*C + c4];
        }
#pragma unroll
        for (int it = 0; it < 8; it++) {
            int k = r0 + half*64 + it*8;
            __half2 q0 = __floats2half2_rn(vb[it].x, vb[it].y);
            __half2 q1 = __floats2half2_rn(vb[it].z, vb[it].w);
            uint2 ow; ow.x = *(unsigned*)&q0; ow.y = *(unsigned*)&q1;
            *(uint2*)&b_sm[k*ALD + c4] = ow;
        }
    }
    __syncthreads();

    const int wm = wid >> 2;     // 0..1 -> rows 32*wm
    const int wn = wid & 3;      // 0..3 -> cols 32*wn

    wmma::fragment<wmma::accumulator, 16, 16, 16, float> acc[2][2];
#pragma unroll
    for (int i = 0; i < 2; i++)
#pragma unroll
        for (int j = 0; j < 2; j++) wmma::fill_fragment(acc[i][j], 0.f);

#pragma unroll
    for (int kk = 0; kk < 8; kk++) {
        wmma::fragment<wmma::matrix_a, 16, 16, 16, __half, wmma::row_major> af[2];
        wmma::fragment<wmma::matrix_b, 16, 16, 16, __half, wmma::row_major> bf[2];
#pragma unroll
        for (int i = 0; i < 2; i++)
            wmma::load_matrix_sync(af[i], &a_sm[(wm*32 + i*16)*ALD + kk*16], ALD);
#pragma unroll
        for (int j = 0; j < 2; j++)
            wmma::load_matrix_sync(bf[j], &b_sm[(kk*16)*ALD + wn*32 + j*16], ALD);
#pragma unroll
        for (int i = 0; i < 2; i++)
#pragma unroll
            for (int j = 0; j < 2; j++)
                wmma::mma_sync(acc[i][j], af[i], bf[j], acc[i][j]);
    }
    __syncthreads();

    float* c_sm = (float*)dyn;                      // [64][CLD]
#pragma unroll
    for (int i = 0; i < 2; i++)
#pragma unroll
        for (int j = 0; j < 2; j++)
            wmma::store_matrix_sync(&c_sm[(wm*32 + i*16)*CLD + wn*32 + j*16],
                                    acc[i][j], CLD, wmma::mem_row_major);
    __syncthreads();

#pragma unroll
    for (int it = 0; it < 8; it++) {
        int idx = tid + it * 256;
        int r = idx >> 5, cc4 = (idx & 31) << 2;
        float4 v = *(const float4*)&c_sm[r*CLD + cc4];
        __half2 h0 = __floats2half2_rn(v.x, v.y);
        __half2 h1 = __floats2half2_rn(v.z, v.w);
        uint2 o; o.x = *(unsigned*)&h0; o.y = *(unsigned*)&h1;
        *(uint2*)&g_h[(size_t)(row0 + r)*C + cc4] = o;
    }

    // ---- CTA 0: pool constants (fp32) ----
    if (blockIdx.x == 0) {
        float* part = (float*)dyn;  // 8*256 floats (post-sync reuse)
        __syncthreads();
        const int cc   = tid & 127;
        const int half = tid >> 7;
        const int j0   = half * 64;
        float q[8];
#pragma unroll
        for (int i = 0; i < 8; i++) q[i] = 0.f;
#pragma unroll 4
        for (int jj = 0; jj < 64; jj++) {
            int j = j0 + jj;
            float w = wg[(size_t)j*C + cc];
            q[0] = fmaf(w_pos[0*C + j], w, q[0]);
            q[1] = fmaf(w_pos[1*C + j], w, q[1]);
            q[2] = fmaf(w_pos[2*C + j], w, q[2]);
            q[3] = fmaf(w_pos[6*C + j], w, q[3]);
            q[4] = fmaf(w_pos[7*C + j], w, q[4]);
            q[5] = fmaf(w_pos[8*C + j], w, q[5]);
            q[6] = fmaf(w_pos[9*C + j], w, q[6]);
            q[7] = fmaf(b_pos[j],       w, q[7]);
        }
#pragma unroll
        for (int i = 0; i < 8; i++) part[i*256 + tid] = q[i];
        __syncthreads();
        if (tid < 128) {
            float r[8];
#pragma unroll
            for (int i = 0; i < 8; i++)
                r[i] = part[i*256 + tid] + part[i*256 + tid + 128];
            g_A[0*C + tid] = r[0] - r[3];
            g_A[1*C + tid] = r[1] - r[4];
            g_A[2*C + tid] = r[2] - r[5];
            g_wd[tid]      = r[6];
            g_b2[tid]      = r[7] + b_gcm[tid];
        }
    }
}

// ---------------------------------------------------------------------------
// K2 (pool, standalone, high occupancy): one warp per point, lane = 4 ch.
// First 16 CTAs also pre-convert w_out -> fp16 g_wo (for K3's B staging).
// ---------------------------------------------------------------------------
__global__ __launch_bounds__(256) void k_pool(
    const float* __restrict__ pts, const float* __restrict__ feat,
    const int*   __restrict__ gidx, const float* __restrict__ wout)
{
    if (blockIdx.x < 16) {
        int b = blockIdx.x * 1024 + threadIdx.x * 4;
        float4 v = *(const float4*)&wout[b];
        __half2 h0 = __floats2half2_rn(v.x, v.y);
        __half2 h1 = __floats2half2_rn(v.z, v.w);
        uint2 o; o.x = *(unsigned*)&h0; o.y = *(unsigned*)&h1;
        *(uint2*)&g_wo[b] = o;
    }

    const int pt   = (blockIdx.x * 256 + threadIdx.x) >> 5;  // 0..32767
    const int lane = threadIdx.x & 31;
    const int base = (pt >> 14) << 14;
    const int c0   = lane << 2;

    const float4 wf = *(const float4*)&g_wd[c0];
    const __half2 wd01 = __floats2half2_rn(wf.x, wf.y);
    const __half2 wd23 = __floats2half2_rn(wf.z, wf.w);
    const __half2 ninf = __half2half2(__ushort_as_half(0xFC00));
    const __half* hs = &g_h[0];

    const float cx = pts[pt*3 + 0], cy = pts[pt*3 + 1], cz = pts[pt*3 + 2];
    int j = gidx[pt*KNB + lane] + base;
    const float* gp = &pts[(size_t)j*3];
    float dx = gp[0] - cx, dy = gp[1] - cy, dz = gp[2] - cz;
    float dist = sqrtf(fmaf(dx, dx, fmaf(dy, dy, dz*dz)));
    unsigned p = (unsigned)j
               | ((unsigned)__half_as_ushort(__float2half_rn(dist)) << 16);

    __half2 acc01 = ninf, acc23 = ninf;
#pragma unroll
    for (int k = 0; k < 32; k++) {
        unsigned q = __shfl_sync(0xffffffffu, p, k);
        __half2 d = __half2half2(__ushort_as_half((unsigned short)(q >> 16)));
        uint2 rv = *(const uint2*)(hs + (((q & 0xFFFFu) << 7) + c0));
        acc01 = __hmax2(acc01, __hfma2(d, wd01, *(__half2*)&rv.x));
        acc23 = __hmax2(acc23, __hfma2(d, wd23, *(__half2*)&rv.y));
    }

    float2 m01 = __half22float2(acc01);
    float2 m23 = __half22float2(acc23);

    const float4 a0 = *(const float4*)&g_A[c0];
    const float4 a1 = *(const float4*)&g_A[C + c0];
    const float4 a2 = *(const float4*)&g_A[2*C + c0];
    const float4 b2 = *(const float4*)&g_b2[c0];
    const float4 f  = *(const float4*)&feat[(size_t)pt*C + c0];

    float r0 = fmaxf(m01.x + fmaf(cx, a0.x, fmaf(cy, a1.x, fmaf(cz, a2.x, b2.x))), 0.f) + f.x;
    float r1 = fmaxf(m01.y + fmaf(cx, a0.y, fmaf(cy, a1.y, fmaf(cz, a2.y, b2.y))), 0.f) + f.y;
    float r2 = fmaxf(m23.x + fmaf(cx, a0.z, fmaf(cy, a1.z, fmaf(cz, a2.z, b2.z))), 0.f) + f.z;
    float r3 = fmaxf(m23.y + fmaf(cx, a0.w, fmaf(cy, a1.w, fmaf(cz, a2.w, b2.w))), 0.f) + f.w;

    __half2 h0 = __floats2half2_rn(r0, r1);
    __half2 h1 = __floats2half2_rn(r2, r3);
    uint2 o; o.x = *(unsigned*)&h0; o.y = *(unsigned*)&h1;
    *(uint2*)&g_r[(size_t)pt*C + c0] = o;
}

// ---------------------------------------------------------------------------
// K3 (wmma + LN, 128-row occ-2, batched staging): out = relu(LN(...)·g + b).
// ---------------------------------------------------------------------------
__global__ __launch_bounds__(256, 2) void k_gemm_ln(
    const float* __restrict__ bout,
    const float* __restrict__ lng,  const float* __restrict__ lnb,
    float* __restrict__ out)
{
    extern __shared__ char dyn[];
    __half* a_h = (__half*)dyn;                     // [128][ALD]
    __half* b_h = (__half*)dyn + 128*ALD;           // [128][ALD]

    const int tid  = threadIdx.x;
    const int wid  = tid >> 5;
    const int row0 = blockIdx.x * 128;

    // stage A + B: batch loads (8 uint4 each), then store
    {
        const int rr = tid >> 4, c8 = (tid & 15) << 3;   // rows stride 16
        uint4 va[8], vb[8];
#pragma unroll
        for (int it = 0; it < 8; it++)
            va[it] = *(const uint4*)&g_r[(size_t)(row0 + rr + it*16)*C + c8];
#pragma unroll
        for (int it = 0; it < 8; it++)
            vb[it] = *(const uint4*)&g_wo[(size_t)(rr + it*16)*C + c8];
#pragma unroll
        for (int it = 0; it < 8; it++) {
            *(uint4*)&a_h[(rr + it*16)*ALD + c8] = va[it];
            *(uint4*)&b_h[(rr + it*16)*ALD + c8] = vb[it];
        }
    }
    __syncthreads();

    const int wm = wid >> 1;
    const int wn = wid & 1;

    wmma::fragment<wmma::accumulator, 16, 16, 16, float> acc[2][4];
#pragma unroll
    for (int i = 0; i < 2; i++)
#pragma unroll
        for (int j = 0; j < 4; j++) wmma::fill_fragment(acc[i][j], 0.f);

#pragma unroll
    for (int kk = 0; kk < 8; kk++) {
        wmma::fragment<wmma::matrix_a, 16, 16, 16, __half, wmma::row_major> af[2];
        wmma::fragment<wmma::matrix_b, 16, 16, 16, __half, wmma::row_major> bf[4];
#pragma unroll
        for (int i = 0; i < 2; i++)
            wmma::load_matrix_sync(af[i], &a_h[(wm*32 + i*16)*ALD + kk*16], ALD);
#pragma unroll
        for (int j = 0; j < 4; j++)
            wmma::load_matrix_sync(bf[j], &b_h[(kk*16)*ALD + wn*64 + j*16], ALD);
#pragma unroll
        for (int i = 0; i < 2; i++)
#pragma unroll
            for (int j = 0; j < 4; j++)
                wmma::mma_sync(acc[i][j], af[i], bf[j], acc[i][j]);
    }
    __syncthreads();

    // epilogue: frags -> fp32 smem, bias + LN (256-thread stats) + relu
    float* c_sm = (float*)dyn;                      // [128][CLD]
    float* smu  = (float*)dyn + 128*CLD;            // [128]
    float* srs  = smu + 128;                        // [128]
    float* sp   = srs + 128;                        // [256]
    float* sq   = sp + 256;                         // [256]

#pragma unroll
    for (int i = 0; i < 2; i++)
#pragma unroll
        for (int j = 0; j < 4; j++)
            wmma::store_matrix_sync(&c_sm[(wm*32 + i*16)*CLD + wn*64 + j*16],
                                    acc[i][j], CLD, wmma::mem_row_major);
    __syncthreads();

    {
        int r = tid & 127, half = tid >> 7;
        int cbeg = half * 64;
        float sum = 0.f, ss = 0.f;
#pragma unroll 8
        for (int c = cbeg; c < cbeg + 64; c += 4) {
            float4 x = *(const float4*)&c_sm[r*CLD + c];
            float4 b = *(const float4*)&bout[c];
            float v0 = x.x + b.x, v1 = x.y + b.y, v2 = x.z + b.z, v3 = x.w + b.w;
            sum += v0 + v1 + v2 + v3;
            ss = fmaf(v0, v0, fmaf(v1, v1, fmaf(v2, v2, fmaf(v3, v3, ss))));
        }
        sp[tid] = sum; sq[tid] = ss;
    }
    __syncthreads();
    if (tid < 128) {
        float sum = sp[tid] + sp[tid + 128];
        float ss  = sq[tid] + sq[tid + 128];
        float mu  = sum * (1.f/128.f);
        float var = fmaf(ss, 1.f/128.f, -mu*mu);
        smu[tid] = mu;
        srs[tid] = rsqrtf(var + LN_EPS);
    }
    __syncthreads();

#pragma unroll
    for (int it = 0; it < 16; it++) {
        int idx = tid + it * 256;
        int r = idx >> 5, c4 = (idx & 31) << 2;
        float4 x = *(const float4*)&c_sm[r*CLD + c4];
        float4 bb = *(const float4*)&bout[c4];
        float4 g = *(const float4*)&lng[c4];
        float4 lb = *(const float4*)&lnb[c4];
        float mu = smu[r], rs = srs[r];
        float4 y;
        y.x = fmaxf(fmaf((x.x + bb.x - mu) * rs, g.x, lb.x), 0.f);
        y.y = fmaxf(fmaf((x.y + bb.y - mu) * rs, g.y, lb.y), 0.f);
        y.z = fmaxf(fmaf((x.z + bb.z - mu) * rs, g.z, lb.z), 0.f);
        y.w = fmaxf(fmaf((x.w + bb.w - mu) * rs, g.w, lb.w), 0.f);
        *(float4*)&out[(size_t)(row0 + r)*C + c4] = y;
    }
}

// ---------------------------------------------------------------------------
extern "C" void kernel_launch(void* const* d_in, const int* in_sizes, int n_in,
                              void* d_out, int out_size)
{
    const float* points = (const float*)d_in[0];
    const float* feat   = (const float*)d_in[1];
    const int*   gidx   = (const int*)  d_in[2];
    const float* w_pos  = (const float*)d_in[3];
    const float* b_pos  = (const float*)d_in[4];
    const float* w_gcm  = (const float*)d_in[5];
    const float* b_gcm  = (const float*)d_in[6];
    const float* w_out  = (const float*)d_in[7];
    const float* b_out  = (const float*)d_in[8];
    const float* ln_g   = (const float*)d_in[9];
    const float* ln_b   = (const float*)d_in[10];
    float* out = (float*)d_out;

    cudaFuncSetAttribute(k_gemm_s,  cudaFuncAttributeMaxDynamicSharedMemorySize, GS_SMEM);
    cudaFuncSetAttribute(k_gemm_ln, cudaFuncAttributeMaxDynamicSharedMemorySize, LN_SMEM);

    k_gemm_s <<<MTOT/64,     256, GS_SMEM>>>(feat, w_gcm, points, w_pos, b_pos, b_gcm);
    k_pool   <<<MTOT*32/256, 256>>>(points, feat, gidx, w_out);
    k_gemm_ln<<<MTOT/128,    256, LN_SMEM>>>(b_out, ln_g, ln_b, out);
}